// round 14
// baseline (speedup 1.0000x reference)
#include <cuda_runtime.h>
#include <cstdint>

// z: (64,13,128,128) fp32
#define BB 64
#define CC 13
#define HWSZ 16384                       // 128*128
#define NPIX (BB*HWSZ)                   // 1,048,576
#define NTOT (CC*NPIX)                   // 13,631,488
#define NPLANES (BB*CC)                  // 832
#define THREADS 256

#define A_BLOCKS (NPLANES*4)             // 3328 blocks: one quarter of one (b,c) plane
#define SLOTS 256                        // per-channel partial slots (64 imgs * 4 quarters)
#define NQ (BB*4)                        // 256 (image,quarter) tickets

// Deterministic scratch (fully overwritten / self-resetting every launch).
__device__ float2 g_ce[A_BLOCKS];                 // per-block {commit, ent}
__device__ float g_chsum[CC * SLOTS];             // channel-major p0 partials
__device__ unsigned char g_signs[NTOT/4];         // 4 sign bits/byte (low nibble)
__device__ unsigned int g_qcnt[NQ];               // wraps at 13 increments
__device__ unsigned int g_cnt;                    // wraps at 3328 increments

__device__ __forceinline__ float warp_sum(float v) {
    #pragma unroll
    for (int o = 16; o; o >>= 1) v += __shfl_xor_sync(0xffffffffu, v, o);
    return v;
}

__device__ __forceinline__ void proc(float zv, float& q, float& commit,
                                     float& ent, float& ch, unsigned& byte, int k) {
    bool pos = zv > 0.0f;
    q = pos ? 1.0f : -1.0f;
    float az = fabsf(zv);
    float d = 1.0f - az;
    commit = fmaf(d, d, commit);
    float a = 4.0f * az;                  // |l0 - l1|
    float e = __expf(-a);                 // in (0,1]
    float r = __fdividef(1.0f, 1.0f + e); // sigmoid(a)
    float ps = e * r;                     // 1 - sigmoid(a)
    ent += fmaf(a, ps, __logf(1.0f + e)); // H(p)
    ch += pos ? r : ps;                   // p0 = sigmoid(4z)
    byte |= (pos ? 1u : 0u) << k;
}

__global__ void __launch_bounds__(THREADS)
lfq_all(const float* __restrict__ z, float* __restrict__ out) {
    int tid = threadIdx.x;
    int blk = blockIdx.x;
    int p       = blk >> 2;               // plane id = b*13 + c
    int quarter = blk & 3;
    int b = p / CC, c = p - b * CC;
    size_t base = (size_t)p * HWSZ + quarter * 4096 + tid * 4;

    // ---------------- main quantize pass ----------------
    float4 v[4];
    #pragma unroll
    for (int i = 0; i < 4; i++)
        v[i] = *reinterpret_cast<const float4*>(z + base + i * 1024);

    float commit = 0.0f, ent = 0.0f, ch = 0.0f;
    int sbase = p * 4096 + quarter * 1024 + tid;
    #pragma unroll
    for (int i = 0; i < 4; i++) {
        float4 q;
        unsigned byte = 0;
        proc(v[i].x, q.x, commit, ent, ch, byte, 0);
        proc(v[i].y, q.y, commit, ent, ch, byte, 1);
        proc(v[i].z, q.z, commit, ent, ch, byte, 2);
        proc(v[i].w, q.w, commit, ent, ch, byte, 3);
        *reinterpret_cast<float4*>(out + base + i * 1024) = q;
        g_signs[sbase + i * 256] = (unsigned char)byte;   // byte s covers pixels 4s..4s+3
    }

    // ---------------- block reduction of 3 scalars ----------------
    commit = warp_sum(commit);
    ent    = warp_sum(ent);
    ch     = warp_sum(ch);
    __shared__ float sw[3][8];
    int w = tid >> 5, lane = tid & 31;
    if (lane == 0) { sw[0][w] = commit; sw[1][w] = ent; sw[2][w] = ch; }
    __syncthreads();
    if (tid == 0) {
        float c0 = 0, e0 = 0, h0 = 0;
        #pragma unroll
        for (int i = 0; i < 8; i++) { c0 += sw[0][i]; e0 += sw[1][i]; h0 += sw[2][i]; }
        g_ce[blk] = make_float2(c0, e0);
        g_chsum[c * SLOTS + b * 4 + quarter] = h0;    // channel-major
    }

    // ---------------- quarter ticket: last of 13 siblings packs ----------------
    __shared__ unsigned s_oldq, s_oldg;
    __threadfence();                       // release: g_signs/g_ce/g_chsum
    __syncthreads();
    if (tid == 0)
        s_oldq = atomicInc(&g_qcnt[b * 4 + quarter], 12);   // wraps to 0 after 13
    __syncthreads();

    if (s_oldq == 12) {                    // whole block packs this quarter (4096 px)
        __threadfence();                   // acquire: siblings' g_signs
        float* idx_out = out + NTOT + 2;   // 8B-aligned -> float2 stores
        int qb = b * CC * 4096 + quarter * 1024 + tid;      // byte base for this thread
        #pragma unroll
        for (int i = 0; i < 4; i++) {      // 4 sub-blocks of 1024 px each
            int i0 = 0, i1 = 0, i2 = 0, i3 = 0;
            #pragma unroll
            for (int cc2 = 0; cc2 < CC; cc2++) {             // MSB = channel 0
                unsigned byte = g_signs[qb + cc2 * 4096 + i * 256];
                i0 = (i0 << 1) | (byte & 1);
                i1 = (i1 << 1) | ((byte >> 1) & 1);
                i2 = (i2 << 1) | ((byte >> 2) & 1);
                i3 = (i3 << 1) | ((byte >> 3) & 1);
            }
            int pix = b * HWSZ + quarter * 4096 + i * 1024 + tid * 4;
            *reinterpret_cast<float2*>(idx_out + pix)     = make_float2((float)i0, (float)i1);
            *reinterpret_cast<float2*>(idx_out + pix + 2) = make_float2((float)i2, (float)i3);
        }
    }

    // ---------------- global ticket: last block finalizes ----------------
    if (tid == 0)
        s_oldg = atomicInc(&g_cnt, A_BLOCKS - 1);    // wraps to 0 after 3328
    __syncthreads();
    if (s_oldg != A_BLOCKS - 1) return;

    __threadfence();                       // acquire: all g_ce / g_chsum

    __shared__ float sce[2][8];
    __shared__ float sch[CC];
    __shared__ float sment;

    // commit/ent: 3328 contiguous float2, 13 coalesced iterations
    float fc = 0.0f, fe = 0.0f;
    #pragma unroll
    for (int r = tid; r < A_BLOCKS; r += THREADS) {
        float2 u = g_ce[r];
        fc += u.x; fe += u.y;
    }
    fc = warp_sum(fc);
    fe = warp_sum(fe);
    if (lane == 0) { sce[0][w] = fc; sce[1][w] = fe; }

    // channel sums: 8 warps cover 13 channels; each channel = 256 contiguous floats
    for (int ch2 = w; ch2 < CC; ch2 += 8) {
        const float4* cp = reinterpret_cast<const float4*>(&g_chsum[ch2 * SLOTS]);
        float4 u0 = cp[lane];
        float4 u1 = cp[lane + 32];
        float chs = (u0.x + u0.y) + (u0.z + u0.w) + (u1.x + u1.y) + (u1.z + u1.w);
        chs = warp_sum(chs);
        if (lane == 0) sch[ch2] = chs;
    }
    __syncthreads();

    // mean-entropy: 13 lanes of warp 0, parallel fp32 logs
    if (tid < 32) {
        float me = 0.0f;
        if (tid < CC) {
            float mp = sch[tid] * (1.0f / (float)NPIX);
            mp = fminf(fmaxf(mp, 1e-12f), 1.0f - 1e-7f);
            float mq = 1.0f - mp;
            me = -(mp * __logf(mp) + mq * __logf(mq));
        }
        me = warp_sum(me);
        if (tid == 0) sment = me * (1.0f / (float)CC);
    }
    __syncthreads();

    if (tid == 0) {
        float c0 = 0.0f, e0 = 0.0f;
        #pragma unroll
        for (int i = 0; i < 8; i++) { c0 += sce[0][i]; e0 += sce[1][i]; }
        out[NTOT]     = c0 * (float)(1.25 * 0.1 / (double)NTOT);
        out[NTOT + 1] = (e0 * (float)(1.0 / (double)NTOT) - sment) * 0.1f;
    }
}

extern "C" void kernel_launch(void* const* d_in, const int* in_sizes, int n_in,
                              void* d_out, int out_size) {
    const float* z = (const float*)d_in[0];
    float* out = (float*)d_out;
    lfq_all<<<A_BLOCKS, THREADS>>>(z, out);
}

// round 15
// speedup vs baseline: 1.2662x; 1.2662x over previous
#include <cuda_runtime.h>
#include <cstdint>

// z: (64,13,128,128) fp32
#define BB 64
#define CC 13
#define HWSZ 16384                       // 128*128
#define NPIX (BB*HWSZ)                   // 1,048,576
#define NTOT (CC*NPIX)                   // 13,631,488
#define NPLANES (BB*CC)                  // 832
#define THREADS 256

#define A_BLOCKS (NPLANES*4)             // 3328: one quarter of one (b,c) plane each
#define SLOTS 256                        // per-channel partial slots (64 imgs * 4 quarters)

// Deterministic scratch (fully overwritten every launch; no runtime allocs).
__device__ float2 g_ce[A_BLOCKS];                 // per-block {commit, ent}
__device__ float g_chsum[CC * SLOTS];             // channel-major p0 partials
__device__ unsigned char g_signs[NTOT/4];         // 4 sign bits/byte (low nibble)

__device__ __forceinline__ float warp_sum(float v) {
    #pragma unroll
    for (int o = 16; o; o >>= 1) v += __shfl_xor_sync(0xffffffffu, v, o);
    return v;
}

__device__ __forceinline__ void proc(float zv, float& q, float& commit,
                                     float& ent, float& ch, unsigned& byte, int k) {
    bool pos = zv > 0.0f;
    q = pos ? 1.0f : -1.0f;
    float az = fabsf(zv);
    float d = 1.0f - az;
    commit = fmaf(d, d, commit);
    float a = 4.0f * az;                  // |l0 - l1|
    float e = __expf(-a);                 // in (0,1]
    float r = __fdividef(1.0f, 1.0f + e); // sigmoid(a)
    float ps = e * r;                     // 1 - sigmoid(a)
    ent += fmaf(a, ps, __logf(1.0f + e)); // H(p)
    ch += pos ? r : ps;                   // p0 = sigmoid(4z)
    byte |= (pos ? 1u : 0u) << k;
}

// ---------------- Kernel A: quantize + partial sums + sign bytes ----------------
__global__ void __launch_bounds__(THREADS)
lfq_planes(const float* __restrict__ z, float* __restrict__ out) {
    int tid = threadIdx.x;
    int blk = blockIdx.x;
    int p       = blk >> 2;               // plane id = b*13 + c
    int quarter = blk & 3;
    size_t base = (size_t)p * HWSZ + quarter * 4096 + tid * 4;

    float4 v[4];
    #pragma unroll
    for (int i = 0; i < 4; i++)
        v[i] = *reinterpret_cast<const float4*>(z + base + i * 1024);

    float commit = 0.0f, ent = 0.0f, ch = 0.0f;
    int sbase = p * 4096 + quarter * 1024 + tid;
    #pragma unroll
    for (int i = 0; i < 4; i++) {
        float4 q;
        unsigned byte = 0;
        proc(v[i].x, q.x, commit, ent, ch, byte, 0);
        proc(v[i].y, q.y, commit, ent, ch, byte, 1);
        proc(v[i].z, q.z, commit, ent, ch, byte, 2);
        proc(v[i].w, q.w, commit, ent, ch, byte, 3);
        *reinterpret_cast<float4*>(out + base + i * 1024) = q;
        g_signs[sbase + i * 256] = (unsigned char)byte;   // byte s covers pixels 4s..4s+3
    }

    commit = warp_sum(commit);
    ent    = warp_sum(ent);
    ch     = warp_sum(ch);
    __shared__ float sw[3][8];
    int w = tid >> 5;
    if ((tid & 31) == 0) { sw[0][w] = commit; sw[1][w] = ent; sw[2][w] = ch; }
    __syncthreads();
    if (tid == 0) {
        float c0 = 0, e0 = 0, h0 = 0;
        #pragma unroll
        for (int i = 0; i < 8; i++) { c0 += sw[0][i]; e0 += sw[1][i]; h0 += sw[2][i]; }
        g_ce[blk] = make_float2(c0, e0);
        int b = p / CC, c = p - b * CC;
        g_chsum[c * SLOTS + b * 4 + quarter] = h0;    // channel-major
    }
}

// ---------------- Kernel B: standalone pack, 4 px/thread (R5 shape) -------------
__global__ void __launch_bounds__(THREADS)
lfq_indices(float* __restrict__ out) {
    float* idx_out = out + NTOT + 2;      // 8B-aligned region -> float2 stores
    int g = blockIdx.x * THREADS + threadIdx.x;   // pixel-group id, [0, NPIX/4)
    int b = g >> 12;                      // 4096 groups per batch image
    int local = g & 4095;
    int i0 = 0, i1 = 0, i2 = 0, i3 = 0;
    #pragma unroll
    for (int c = 0; c < CC; c++) {        // MSB = channel 0
        unsigned byte = g_signs[(b * CC + c) * 4096 + local];
        i0 = (i0 << 1) | (byte & 1);
        i1 = (i1 << 1) | ((byte >> 1) & 1);
        i2 = (i2 << 1) | ((byte >> 2) & 1);
        i3 = (i3 << 1) | ((byte >> 3) & 1);
    }
    int pix = g * 4;
    *reinterpret_cast<float2*>(idx_out + pix)     = make_float2((float)i0, (float)i1);
    *reinterpret_cast<float2*>(idx_out + pix + 2) = make_float2((float)i2, (float)i3);
}

// ---------------- Kernel C: fast finalize (coalesced reads, fp32 logs) ----------
__global__ void __launch_bounds__(512)
lfq_finalize(float* __restrict__ out) {
    int tid = threadIdx.x;
    int w = tid >> 5, lane = tid & 31;
    __shared__ float sce[2][16];
    __shared__ float sch[CC];
    __shared__ float sment;

    // commit/ent: 3328 contiguous float2, coalesced strided reads
    float commit = 0.0f, ent = 0.0f;
    #pragma unroll
    for (int r = tid; r < A_BLOCKS; r += 512) {
        float2 u = g_ce[r];
        commit += u.x;
        ent    += u.y;
    }
    commit = warp_sum(commit);
    ent    = warp_sum(ent);
    if (lane == 0) { sce[0][w] = commit; sce[1][w] = ent; }

    // channel sums: warp w (<13) owns channel w: 256 contiguous floats as float4s
    if (w < CC) {
        const float4* cp = reinterpret_cast<const float4*>(&g_chsum[w * SLOTS]);
        float4 u0 = cp[lane];
        float4 u1 = cp[lane + 32];
        float chs = (u0.x + u0.y) + (u0.z + u0.w) + (u1.x + u1.y) + (u1.z + u1.w);
        chs = warp_sum(chs);
        if (lane == 0) sch[w] = chs;
    }
    __syncthreads();

    // mean-entropy: 13 lanes of warp 0, parallel fp32 logs
    if (tid < 32) {
        float me = 0.0f;
        if (tid < CC) {
            float mp = sch[tid] * (1.0f / (float)NPIX);
            mp = fminf(fmaxf(mp, 1e-12f), 1.0f - 1e-7f);
            float mq = 1.0f - mp;
            me = -(mp * __logf(mp) + mq * __logf(mq));
        }
        me = warp_sum(me);
        if (tid == 0) sment = me * (1.0f / (float)CC);
    }
    __syncthreads();

    if (tid == 0) {
        float c0 = 0.0f, e0 = 0.0f;
        #pragma unroll
        for (int i = 0; i < 16; i++) { c0 += sce[0][i]; e0 += sce[1][i]; }
        out[NTOT]     = c0 * (float)(1.25 * 0.1 / (double)NTOT);
        out[NTOT + 1] = (e0 * (float)(1.0 / (double)NTOT) - sment) * 0.1f;
    }
}

extern "C" void kernel_launch(void* const* d_in, const int* in_sizes, int n_in,
                              void* d_out, int out_size) {
    const float* z = (const float*)d_in[0];
    float* out = (float*)d_out;
    lfq_planes<<<A_BLOCKS, THREADS>>>(z, out);
    lfq_indices<<<NPIX / 4 / THREADS, THREADS>>>(out);
    lfq_finalize<<<1, 512>>>(out);
}